// round 15
// baseline (speedup 1.0000x reference)
#include <cuda_runtime.h>
#include <cuda_bf16.h>
#include <cuda_fp16.h>
#include <cstdint>

// Problem: B=128, N=128, D=1024, H=8, HD=128, M = B*N = 16384
#define PLANE    (16384ull * 1024ull)   // activation plane elems (2B units)
#define WPLANE   (1024ull * 1024ull)    // weight plane elems
__device__ __align__(1024) __nv_bfloat16 g_bf[22ull * PLANE + 32ull * WPLANE];

typedef __nv_bfloat16 bf16;

// ======================= PTX helpers =========================================
__device__ __forceinline__ uint32_t s2u(const void* p) {
    uint32_t a;
    asm("{ .reg .u64 t; cvta.to.shared.u64 t, %1; cvt.u32.u64 %0, t; }"
        : "=r"(a) : "l"(p));
    return a;
}
__device__ __forceinline__ void ldsm4(uint32_t* r, uint32_t addr) {
    asm volatile("ldmatrix.sync.aligned.m8n8.x4.shared.b16 {%0,%1,%2,%3}, [%4];"
                 : "=r"(r[0]), "=r"(r[1]), "=r"(r[2]), "=r"(r[3]) : "r"(addr));
}
__device__ __forceinline__ void ldsm4t(uint32_t* r, uint32_t addr) {
    asm volatile("ldmatrix.sync.aligned.m8n8.x4.trans.shared.b16 {%0,%1,%2,%3}, [%4];"
                 : "=r"(r[0]), "=r"(r[1]), "=r"(r[2]), "=r"(r[3]) : "r"(addr));
}
__device__ __forceinline__ void mma_fp16(float* d, const uint32_t* a, const uint32_t* b) {
    asm volatile(
        "mma.sync.aligned.m16n8k16.row.col.f32.f16.f16.f32 "
        "{%0,%1,%2,%3},{%4,%5,%6,%7},{%8,%9},{%0,%1,%2,%3};"
        : "+f"(d[0]), "+f"(d[1]), "+f"(d[2]), "+f"(d[3])
        : "r"(a[0]), "r"(a[1]), "r"(a[2]), "r"(a[3]), "r"(b[0]), "r"(b[1]));
}
#define CP16(dst, src) \
    asm volatile("cp.async.cg.shared.global [%0], [%1], 16;" :: "r"(dst), "l"(src))
#define CPCOMMIT() asm volatile("cp.async.commit_group;" ::: "memory")
#define CPWAIT3()  asm volatile("cp.async.wait_group 3;" ::: "memory")
#define CPWAIT2()  asm volatile("cp.async.wait_group 2;" ::: "memory")
#define CPWAIT0()  asm volatile("cp.async.wait_group 0;" ::: "memory")

__device__ __forceinline__ uint32_t packh2(float x0, float x1) {
    __half2 h; h.x = __float2half_rn(x0); h.y = __float2half_rn(x1);
    return *(uint32_t*)&h;
}

// ======================= input conversion (3 inputs -> fp16 planes) ==========
__global__ __launch_bounds__(256) void split_all(
    const float* __restrict__ s0, const float* __restrict__ s1,
    const float* __restrict__ s2, __half* __restrict__ ob)
{
    const float* src = (blockIdx.y == 0) ? s0 : (blockIdx.y == 1) ? s1 : s2;
    __half* o = ob + (size_t)blockIdx.y * PLANE;
    size_t i4 = ((size_t)blockIdx.x * 256 + threadIdx.x) * 4;
    float4 v = *(const float4*)(src + i4);
    *(uint32_t*)(o + i4)     = packh2(v.x, v.y);
    *(uint32_t*)(o + i4 + 2) = packh2(v.z, v.w);
}

// ======================= weight transpose -> fp16 planes (all 8) =============
__global__ __launch_bounds__(256) void transpose8(
    const float* __restrict__ s0, const float* __restrict__ s1,
    const float* __restrict__ s2, const float* __restrict__ s3,
    const float* __restrict__ s4, const float* __restrict__ s5,
    const float* __restrict__ s6, const float* __restrict__ s7,
    __half* __restrict__ ob)
{
    const float* srcs[8] = { s0, s1, s2, s3, s4, s5, s6, s7 };
    const float* src = srcs[blockIdx.z];
    __half* o = ob + (size_t)blockIdx.z * WPLANE;
    __shared__ float t[32][33];
    int bx = blockIdx.x * 32, by = blockIdx.y * 32;
    int tx = threadIdx.x, ty = threadIdx.y;
#pragma unroll
    for (int i = ty; i < 32; i += 8)
        t[i][tx] = src[(size_t)(by + i) * 1024 + bx + tx];
    __syncthreads();
#pragma unroll
    for (int i = ty; i < 32; i += 8)
        o[(size_t)(bx + i) * 1024 + by + tx] = __float2half_rn(t[tx][i]);
}

// ======================= single-pass fp16 mma.sync GEMM ======================
// CTA 128x128, 256 thr, warp tile 64x32 (2x4 warp grid), 2 CTAs/SM.
// fp16 m16n8k16: 16 MMA + 6 ldsm per k16 chunk.
// 6-stage ring, per-chunk commit, wait_group 3, FRAGMENT DOUBLE-BUFFERING:
// iter c runs MMAs on fragments loaded at iter c-1 while ldsm'ing chunk c+1
// under the tensor-pipe shadow. Loads at distance 5 (stage (c-1)%6, safe).
// smem stage: A@0 (128 rows x 48B), B@6144 (128 x 48B); stage stride 12288.
// A idx(r,k) = (r/128)*131072 + (k/128)*ACB + (r%128)*ARI + (k%128)   [halves]
// mode=1: merged projections — ct -> (A plane ap, W plane bp, col tile bct);
//         C = single fp16 plane set (head layout).
// mode=0: single planes (final GEMM, f32 out), bct = ct.
#define GEMM_STAGES 6
#define GEMM_SMEM (GEMM_STAGES * 12288)

struct FragG { uint32_t at[4][4]; uint32_t bt[4][2]; };

__device__ __forceinline__ void ldfragG(FragG& f, uint32_t off,
                                        int wm, int wn,
                                        uint32_t aLane, uint32_t bLane)
{
#pragma unroll
    for (int pr = 0; pr < 2; pr++) {
        uint32_t q[4];
        ldsm4(q, off + 6144u + (uint32_t)((wn * 32 + pr * 16) * 48) + bLane);
        f.bt[2 * pr][0]     = q[0]; f.bt[2 * pr][1]     = q[1];
        f.bt[2 * pr + 1][0] = q[2]; f.bt[2 * pr + 1][1] = q[3];
    }
#pragma unroll
    for (int mt = 0; mt < 4; mt++)
        ldsm4(f.at[mt], off + (uint32_t)((wm * 64 + mt * 16) * 48) + aLane);
}

__global__ __launch_bounds__(256, 2) void gemm_fp(
    const __half* __restrict__ A, const __half* __restrict__ B,
    float* __restrict__ Cf, __half* __restrict__ Ch,
    const float* __restrict__ bias, int ACB, int ARI, int CCB, int CRI, int mode)
{
    extern __shared__ __align__(1024) char smem[];
    const uint32_t sb = s2u(smem);
    const int tid = threadIdx.x;
    const int lane = tid & 31, wid = tid >> 5;
    const int rt = blockIdx.y, ct = blockIdx.x;

    int ap, bp, bct;
    if (mode) {
        if (ct < 24)      { ap = 0; bp = ct >> 3;              bct = ct & 7; }
        else if (ct < 40) { ap = 1; bp = 3 + ((ct - 24) >> 3); bct = (ct - 24) & 7; }
        else              { ap = 2; bp = 5 + ((ct - 40) >> 3); bct = (ct - 40) & 7; }
    } else { ap = 0; bp = 0; bct = ct; }

    const int wm = wid & 1, wn = wid >> 1;
    const int s8 = lane >> 3, r8 = lane & 7;
    const uint32_t aLane = (uint32_t)(((s8 & 1) * 8 + r8) * 48 + (s8 >> 1) * 16);
    const uint32_t bLane = (uint32_t)(((s8 >> 1) * 8 + r8) * 48 + (s8 & 1) * 16);

    const int lrow = tid >> 1, lhalf = tid & 1;
    const uint32_t dstoff = (uint32_t)(lrow * 48 + lhalf * 16);
    const __half* Abase = A + (size_t)ap * PLANE;
    const __half* Bbase = B + (size_t)bp * WPLANE;

    float acc[4][4][4];
#pragma unroll
    for (int i = 0; i < 4; i++)
#pragma unroll
        for (int j = 0; j < 4; j++)
#pragma unroll
            for (int k = 0; k < 4; k++) acc[i][j][k] = 0.f;

    auto stage_off = [&](int c) -> uint32_t {
        return (uint32_t)((c % GEMM_STAGES) * 12288);
    };
    auto load_chunk = [&](int c) {
        const int kk = c * 16;
        const uint32_t st = sb + stage_off(c) + dstoff;
        const size_t asrc = (size_t)rt * 131072 + (size_t)(kk >> 7) * ACB
                          + (size_t)lrow * ARI + (kk & 127) + lhalf * 8;
        CP16(st, Abase + asrc);
        const size_t bsrc = (size_t)(bct * 128 + lrow) * 1024 + kk + lhalf * 8;
        CP16(st + 6144u, Bbase + bsrc);
    };

    // prologue: chunks 0..4 in flight (5 groups)
    load_chunk(0); CPCOMMIT();
    load_chunk(1); CPCOMMIT();
    load_chunk(2); CPCOMMIT();
    load_chunk(3); CPCOMMIT();
    load_chunk(4); CPCOMMIT();

    FragG f0, f1;
    CPWAIT3();                  // chunks 0,1 resident
    __syncthreads();
    ldfragG(f0, sb + stage_off(0), wm, wn, aLane, bLane);

    auto step = [&](int c, FragG& cur, FragG& nxt) {
        CPWAIT3();              // chunk c+1 resident (pending <= c+2..c+4)
        __syncthreads();        // all warps done with frags of stage (c-1)%6
        if (c + 1 < 64)
            ldfragG(nxt, sb + stage_off(c + 1), wm, wn, aLane, bLane);
        // MMAs on cur: zero smem dependency (loaded last iteration)
#pragma unroll
        for (int mt = 0; mt < 4; mt++)
#pragma unroll
            for (int nt = 0; nt < 4; nt++)
                mma_fp16(acc[mt][nt], cur.at[mt], cur.bt[nt]);
        if (c + 5 < 64) load_chunk(c + 5);
        CPCOMMIT();
    };

    for (int c = 0; c < 64; c += 2) {
        step(c, f0, f1);
        step(c + 1, f1, f0);
    }

    // ---- epilogue ----
    const int g = lane >> 2, cp2 = (lane & 3) * 2;
    const size_t cbase = (size_t)bp * PLANE + (size_t)rt * 131072 + (size_t)bct * CCB;
#pragma unroll
    for (int mt = 0; mt < 4; mt++) {
#pragma unroll
        for (int nt = 0; nt < 4; nt++) {
            int r0 = wm * 64 + mt * 16 + g;
            int col = wn * 32 + nt * 8 + cp2;
            float v0 = acc[mt][nt][0], v1 = acc[mt][nt][1];
            float v2 = acc[mt][nt][2], v3 = acc[mt][nt][3];
            size_t o0 = cbase + (size_t)r0 * CRI + col;
            size_t o1 = cbase + (size_t)(r0 + 8) * CRI + col;
            if (Cf) {
                float b0 = bias[bct * 128 + col], b1 = bias[bct * 128 + col + 1];
                *(float2*)(Cf + o0) = make_float2(v0 + b0, v1 + b1);
                *(float2*)(Cf + o1) = make_float2(v2 + b0, v3 + b1);
            } else {
                *(uint32_t*)(Ch + o0) = packh2(v0, v1);
                *(uint32_t*)(Ch + o1) = packh2(v2, v3);
            }
        }
    }
}

// ======================= fp16 mma attention (register-resident P) ============
// One CTA per (b,h). Warp w owns rows w*16..w*16+15 (full 128 cols).
// All operands single fp16 planes. sim: 16 MMA/iter; P*V: 16 MMA/chunk.
// smem: Q stages@0 (4 x 6144: 128 rows x 48B),
//       K/V stages@24576 (4 x 4352: 16 rows x 272B). total 41984.
#define ATT_SMEM 41984
#define ATT_KST  24576u

__global__ __launch_bounds__(256, 1) void attn_mma(
    const __half* __restrict__ qkv, __half* __restrict__ atth)
{
    extern __shared__ __align__(1024) char smem[];
    const uint32_t sb = s2u(smem);
    const int tid = threadIdx.x;
    const int lane = tid & 31, w = tid >> 5;
    const size_t bhoff = (size_t)blockIdx.x * 16384;

    // plane order in qkv: 0 qw, 1 kw, 2 vw, 3 qp, 4 kp, 5 qc, 6 kc
    const int qpl[3] = { 0, 3, 5 }, kpl[3] = { 1, 4, 6 };

    const int s8 = lane >> 3, r8 = lane & 7;
    const uint32_t aLane = (uint32_t)(((s8 & 1) * 8 + r8) * 48 + (s8 >> 1) * 16);
    const uint32_t kr = (uint32_t)(lane & 15);
    const uint32_t nf = (uint32_t)((lane >> 4) * 8);
    const uint32_t wrow48 = (uint32_t)(w * 16 * 48);

    const int qrow = tid >> 1, qhalf = tid & 1;
    const uint32_t qdst = (uint32_t)(qrow * 48 + qhalf * 16);
    const int krow = tid >> 4, kseg = tid & 15;
    const uint32_t kdst = (uint32_t)(krow * 272 + kseg * 16);

    auto loadQK = [&](int it) {
        int s = it >> 3, c = it & 7;
        uint32_t qs = sb + (uint32_t)((it & 3) * 6144) + qdst;
        size_t qsrc = (size_t)qpl[s] * PLANE + bhoff + (size_t)qrow * 128 + c * 16 + qhalf * 8;
        CP16(qs, qkv + qsrc);
        uint32_t ks = sb + ATT_KST + (uint32_t)((it & 3) * 4352) + kdst;
        size_t ksrc = (size_t)kpl[s] * PLANE + bhoff + (size_t)(c * 16 + krow) * 128 + kseg * 8;
        CP16(ks, qkv + ksrc);
    };
    auto loadV = [&](int v) {
        uint32_t ks = sb + ATT_KST + (uint32_t)((v & 3) * 4352) + kdst;
        size_t ksrc = 2ull * PLANE + bhoff + (size_t)(v * 16 + krow) * 128 + kseg * 8;
        CP16(ks, qkv + ksrc);
    };

    float acc[16][4];
#pragma unroll
    for (int i = 0; i < 16; i++)
#pragma unroll
        for (int j = 0; j < 4; j++) acc[i][j] = 0.f;

    loadQK(0); CPCOMMIT();
    loadQK(1); CPCOMMIT();
    loadQK(2); CPCOMMIT();

    // ---- Phase 1: sim (24 iters = 3 streams x 8 k-chunks; 16 MMA/iter) ----
    for (int it = 0; it < 24; it++) {
        CPWAIT2();
        __syncthreads();
        if (it + 3 < 24) loadQK(it + 3);
        CPCOMMIT();

        const uint32_t qs = sb + (uint32_t)((it & 3) * 6144);
        const uint32_t ks = sb + ATT_KST + (uint32_t)((it & 3) * 4352);
        uint32_t ah[4];
        ldsm4(ah, qs + wrow48 + aLane);
#pragma unroll
        for (int gp = 0; gp < 4; gp++) {
            uint32_t b0[4], b1[4];
            uint32_t a0 = ks + kr * 272 + ((2 * gp) * 16 + nf) * 2;
            uint32_t a1 = ks + kr * 272 + ((2 * gp + 1) * 16 + nf) * 2;
            ldsm4t(b0, a0);
            ldsm4t(b1, a1);
            mma_fp16(acc[4 * gp],     ah, b0);
            mma_fp16(acc[4 * gp + 1], ah, b0 + 2);
            mma_fp16(acc[4 * gp + 2], ah, b1);
            mma_fp16(acc[4 * gp + 3], ah, b1 + 2);
        }
    }

    // drain QK traffic, then prefetch V into stages 0..2 (overlaps softmax)
    CPWAIT0();
    __syncthreads();
    loadV(0); CPCOMMIT();
    loadV(1); CPCOMMIT();
    loadV(2); CPCOMMIT();

    // ---- Phase 2: softmax (warp-local; lane rows g and g+8) ----
    const float SC = 0.08838834764831845f;   // 128^-0.5
    float m0 = -1e30f, m1 = -1e30f;
#pragma unroll
    for (int nt = 0; nt < 16; nt++) {
#pragma unroll
        for (int j = 0; j < 4; j++) acc[nt][j] *= SC;
        m0 = fmaxf(m0, fmaxf(acc[nt][0], acc[nt][1]));
        m1 = fmaxf(m1, fmaxf(acc[nt][2], acc[nt][3]));
    }
    m0 = fmaxf(m0, __shfl_xor_sync(0xffffffffu, m0, 1));
    m0 = fmaxf(m0, __shfl_xor_sync(0xffffffffu, m0, 2));
    m1 = fmaxf(m1, __shfl_xor_sync(0xffffffffu, m1, 1));
    m1 = fmaxf(m1, __shfl_xor_sync(0xffffffffu, m1, 2));
    float sum0 = 0.f, sum1 = 0.f;
#pragma unroll
    for (int nt = 0; nt < 16; nt++) {
        acc[nt][0] = __expf(acc[nt][0] - m0); sum0 += acc[nt][0];
        acc[nt][1] = __expf(acc[nt][1] - m0); sum0 += acc[nt][1];
        acc[nt][2] = __expf(acc[nt][2] - m1); sum1 += acc[nt][2];
        acc[nt][3] = __expf(acc[nt][3] - m1); sum1 += acc[nt][3];
    }
    sum0 += __shfl_xor_sync(0xffffffffu, sum0, 1);
    sum0 += __shfl_xor_sync(0xffffffffu, sum0, 2);
    sum1 += __shfl_xor_sync(0xffffffffu, sum1, 1);
    sum1 += __shfl_xor_sync(0xffffffffu, sum1, 2);
    const float inv0 = 1.f / sum0, inv1 = 1.f / sum1;

    // ---- repack P into fp16 A-fragments (C-frag layout == A-frag layout) ----
    uint32_t pf[8][4];
#pragma unroll
    for (int c = 0; c < 8; c++) {
        pf[c][0] = packh2(acc[2*c][0]   * inv0, acc[2*c][1]   * inv0);
        pf[c][1] = packh2(acc[2*c][2]   * inv1, acc[2*c][3]   * inv1);
        pf[c][2] = packh2(acc[2*c+1][0] * inv0, acc[2*c+1][1] * inv0);
        pf[c][3] = packh2(acc[2*c+1][2] * inv1, acc[2*c+1][3] * inv1);
    }
#pragma unroll
    for (int i = 0; i < 16; i++)
#pragma unroll
        for (int j = 0; j < 4; j++) acc[i][j] = 0.f;

    // ---- Phase 3: out = P * V (8 k-chunks; 16 MMA/chunk) ----
    for (int v = 0; v < 8; v++) {
        CPWAIT2();
        __syncthreads();
        if (v + 3 < 8) loadV(v + 3);
        CPCOMMIT();

        const uint32_t ks = sb + ATT_KST + (uint32_t)((v & 3) * 4352);
#pragma unroll
        for (int gp = 0; gp < 4; gp++) {
            uint32_t b0[4], b1[4];
            uint32_t a0 = ks + kr * 272 + ((2 * gp) * 16 + nf) * 2;
            uint32_t a1 = ks + kr * 272 + ((2 * gp + 1) * 16 + nf) * 2;
            ldsm4t(b0, a0);
            ldsm4t(b1, a1);
            mma_fp16(acc[4 * gp],     pf[v], b0);
            mma_fp16(acc[4 * gp + 1], pf[v], b0 + 2);
            mma_fp16(acc[4 * gp + 2], pf[v], b1);
            mma_fp16(acc[4 * gp + 3], pf[v], b1 + 2);
        }
    }

    // ---- write att as fp16 plane ----
    {
        const int g = lane >> 2, c2 = (lane & 3) * 2;
        const size_t r0 = bhoff + (size_t)(w * 16 + g) * 128;
#pragma unroll
        for (int nt = 0; nt < 16; nt++) {
            int col = nt * 8 + c2;
            *(uint32_t*)(atth + r0 + col) = packh2(acc[nt][0], acc[nt][1]);
            *(uint32_t*)(atth + r0 + 8 * 128 + col) = packh2(acc[nt][2], acc[nt][3]);
        }
    }
}

// ======================= launch ==============================================
extern "C" void kernel_launch(void* const* d_in, const int* in_sizes, int n_in,
                              void* d_out, int out_size)
{
    (void)in_sizes; (void)n_in; (void)out_size;
    const float* inp[3] = { (const float*)d_in[0], (const float*)d_in[1],
                            (const float*)d_in[2] };
    const float* W[8] = { (const float*)d_in[3], (const float*)d_in[4],
                          (const float*)d_in[5], (const float*)d_in[6],
                          (const float*)d_in[7], (const float*)d_in[8],
                          (const float*)d_in[9], (const float*)d_in[10] };
    const float* bo = (const float*)d_in[11];
    float* out = (float*)d_out;

    void* symp = nullptr;
    cudaGetSymbolAddress(&symp, g_bf);
    bf16* P = (bf16*)symp;
    __half* infp = (__half*)P;                    // 3 fp16 input planes  [0,3)
    __half* qkvh = (__half*)(P + 3ull * PLANE);   // 7 fp16 q/k/v planes  [3,10)
    __half* atth = (__half*)(P + 10ull * PLANE);  // 1 fp16 att plane     [10,11)
    __half* wfp  = (__half*)(P + 11ull * PLANE);  // 8 fp16 weight planes

    cudaFuncSetAttribute(gemm_fp, cudaFuncAttributeMaxDynamicSharedMemorySize, GEMM_SMEM);
    cudaFuncSetAttribute(attn_mma, cudaFuncAttributeMaxDynamicSharedMemorySize, ATT_SMEM);

    // 0) convert inputs to fp16 planes
    split_all<<<dim3(16384, 3), 256>>>(inp[0], inp[1], inp[2], infp);

    // 1) transpose all 8 weights -> fp16 planes [N][K] (one launch)
    dim3 tgrid(32, 32, 8), tblk(32, 8);
    transpose8<<<tgrid, tblk>>>(W[0], W[1], W[2], W[3],
                                W[4], W[5], W[6], W[7], wfp);

    // 2) ALL projections in one launch -> fp16 q/k/v planes (head layout)
    gemm_fp<<<dim3(56, 128), 256, GEMM_SMEM>>>(
        infp, wfp, nullptr, qkvh, nullptr, 128, 1024, 16384, 128, 1);

    // 3) attention (all-fp16) -> fp16 att plane
    attn_mma<<<1024, 256, ATT_SMEM>>>(qkvh, atth);

    // 4) final GEMM: att * Wo^T + bias -> f32 out (row-major)
    gemm_fp<<<dim3(8, 128), 256, GEMM_SMEM>>>(
        atth, wfp + 7ull * WPLANE,
        out, nullptr, bo, 16384, 128, 128, 1024, 0);
}

// round 16
// speedup vs baseline: 1.1447x; 1.1447x over previous
#include <cuda_runtime.h>
#include <cuda_bf16.h>
#include <cuda_fp16.h>
#include <cstdint>

// Problem: B=128, N=128, D=1024, H=8, HD=128, M = B*N = 16384
#define PLANE    (16384ull * 1024ull)   // activation plane elems (2B units)
#define WPLANE   (1024ull * 1024ull)    // weight plane elems
__device__ __align__(1024) __nv_bfloat16 g_bf[22ull * PLANE + 32ull * WPLANE];

typedef __nv_bfloat16 bf16;

// ======================= PTX helpers =========================================
__device__ __forceinline__ uint32_t s2u(const void* p) {
    uint32_t a;
    asm("{ .reg .u64 t; cvta.to.shared.u64 t, %1; cvt.u32.u64 %0, t; }"
        : "=r"(a) : "l"(p));
    return a;
}
__device__ __forceinline__ void ldsm4(uint32_t* r, uint32_t addr) {
    asm volatile("ldmatrix.sync.aligned.m8n8.x4.shared.b16 {%0,%1,%2,%3}, [%4];"
                 : "=r"(r[0]), "=r"(r[1]), "=r"(r[2]), "=r"(r[3]) : "r"(addr));
}
__device__ __forceinline__ void ldsm4t(uint32_t* r, uint32_t addr) {
    asm volatile("ldmatrix.sync.aligned.m8n8.x4.trans.shared.b16 {%0,%1,%2,%3}, [%4];"
                 : "=r"(r[0]), "=r"(r[1]), "=r"(r[2]), "=r"(r[3]) : "r"(addr));
}
__device__ __forceinline__ void mma_fp16(float* d, const uint32_t* a, const uint32_t* b) {
    asm volatile(
        "mma.sync.aligned.m16n8k16.row.col.f32.f16.f16.f32 "
        "{%0,%1,%2,%3},{%4,%5,%6,%7},{%8,%9},{%0,%1,%2,%3};"
        : "+f"(d[0]), "+f"(d[1]), "+f"(d[2]), "+f"(d[3])
        : "r"(a[0]), "r"(a[1]), "r"(a[2]), "r"(a[3]), "r"(b[0]), "r"(b[1]));
}
#define CP16(dst, src) \
    asm volatile("cp.async.cg.shared.global [%0], [%1], 16;" :: "r"(dst), "l"(src))
#define CPCOMMIT() asm volatile("cp.async.commit_group;" ::: "memory")
#define CPWAIT4()  asm volatile("cp.async.wait_group 4;" ::: "memory")
#define CPWAIT2()  asm volatile("cp.async.wait_group 2;" ::: "memory")
#define CPWAIT0()  asm volatile("cp.async.wait_group 0;" ::: "memory")

__device__ __forceinline__ uint32_t packh2(float x0, float x1) {
    __half2 h; h.x = __float2half_rn(x0); h.y = __float2half_rn(x1);
    return *(uint32_t*)&h;
}

// ======================= fused prep: transpose 8 weights + convert 3 inputs ===
// grid (1024, 11), 256 threads.
// y in [0,8): weight y transpose 32x32 tile (tile x = bIdx.x&31, tile y = >>5).
// y in [8,11): input y-8 conversion; block handles 16384 contiguous floats.
__global__ __launch_bounds__(256) void prep_all(
    const float* __restrict__ w0, const float* __restrict__ w1,
    const float* __restrict__ w2, const float* __restrict__ w3,
    const float* __restrict__ w4, const float* __restrict__ w5,
    const float* __restrict__ w6, const float* __restrict__ w7,
    const float* __restrict__ i0, const float* __restrict__ i1,
    const float* __restrict__ i2,
    __half* __restrict__ wout, __half* __restrict__ iout)
{
    const int z = blockIdx.y;
    const int tid = threadIdx.x;
    if (z < 8) {
        const float* srcs[8] = { w0, w1, w2, w3, w4, w5, w6, w7 };
        const float* src = srcs[z];
        __half* o = wout + (size_t)z * WPLANE;
        __shared__ float t[32][33];
        int bx = (blockIdx.x & 31) * 32, by = (blockIdx.x >> 5) * 32;
        int tx = tid & 31, ty = tid >> 5;
#pragma unroll
        for (int i = ty; i < 32; i += 8)
            t[i][tx] = src[(size_t)(by + i) * 1024 + bx + tx];
        __syncthreads();
#pragma unroll
        for (int i = ty; i < 32; i += 8)
            o[(size_t)(bx + i) * 1024 + by + tx] = __float2half_rn(t[tx][i]);
    } else {
        const float* src = (z == 8) ? i0 : (z == 9) ? i1 : i2;
        __half* o = iout + (size_t)(z - 8) * PLANE;
        size_t base = (size_t)blockIdx.x * 16384 + tid * 4;
#pragma unroll
        for (int it = 0; it < 16; it++) {
            size_t i4 = base + (size_t)it * 1024;
            float4 v = *(const float4*)(src + i4);
            *(uint32_t*)(o + i4)     = packh2(v.x, v.y);
            *(uint32_t*)(o + i4 + 2) = packh2(v.z, v.w);
        }
    }
}

// ======================= single-pass fp16 mma.sync GEMM (round-14 proven) ====
// CTA 128x128, 256 thr, warp tile 64x32 (2x4 warp grid), 2 CTAs/SM.
// fp16 m16n8k16: 16 MMA + 6 ldsm per k16 chunk.
// 6-stage ring, per-chunk commit, wait_group 4 (distance 5).
// smem stage: A@0 (128 rows x 48B), B@6144 (128 x 48B); stage stride 12288.
// A idx(r,k) = (r/128)*131072 + (k/128)*ACB + (r%128)*ARI + (k%128)   [halves]
// mode=1: merged projections — ct -> (A plane ap, W plane bp, col tile bct);
//         C = single fp16 plane set (head layout).
// mode=0: single planes (final GEMM, f32 out), bct = ct.
#define GEMM_STAGES 6
#define GEMM_SMEM (GEMM_STAGES * 12288)

__global__ __launch_bounds__(256, 2) void gemm_fp(
    const __half* __restrict__ A, const __half* __restrict__ B,
    float* __restrict__ Cf, __half* __restrict__ Ch,
    const float* __restrict__ bias, int ACB, int ARI, int CCB, int CRI, int mode)
{
    extern __shared__ __align__(1024) char smem[];
    const uint32_t sb = s2u(smem);
    const int tid = threadIdx.x;
    const int lane = tid & 31, wid = tid >> 5;
    const int rt = blockIdx.y, ct = blockIdx.x;

    int ap, bp, bct;
    if (mode) {
        if (ct < 24)      { ap = 0; bp = ct >> 3;              bct = ct & 7; }
        else if (ct < 40) { ap = 1; bp = 3 + ((ct - 24) >> 3); bct = (ct - 24) & 7; }
        else              { ap = 2; bp = 5 + ((ct - 40) >> 3); bct = (ct - 40) & 7; }
    } else { ap = 0; bp = 0; bct = ct; }

    const int wm = wid & 1, wn = wid >> 1;
    const int s8 = lane >> 3, r8 = lane & 7;
    const uint32_t aLane = (uint32_t)(((s8 & 1) * 8 + r8) * 48 + (s8 >> 1) * 16);
    const uint32_t bLane = (uint32_t)(((s8 >> 1) * 8 + r8) * 48 + (s8 & 1) * 16);

    const int lrow = tid >> 1, lhalf = tid & 1;
    const uint32_t dstoff = (uint32_t)(lrow * 48 + lhalf * 16);
    const __half* Abase = A + (size_t)ap * PLANE;
    const __half* Bbase = B + (size_t)bp * WPLANE;

    float acc[4][4][4];
#pragma unroll
    for (int i = 0; i < 4; i++)
#pragma unroll
        for (int j = 0; j < 4; j++)
#pragma unroll
            for (int k = 0; k < 4; k++) acc[i][j][k] = 0.f;

    auto stage_off = [&](int c) -> uint32_t {
        return (uint32_t)((c % GEMM_STAGES) * 12288);
    };
    auto load_chunk = [&](int c) {
        const int kk = c * 16;
        const uint32_t st = sb + stage_off(c) + dstoff;
        const size_t asrc = (size_t)rt * 131072 + (size_t)(kk >> 7) * ACB
                          + (size_t)lrow * ARI + (kk & 127) + lhalf * 8;
        CP16(st, Abase + asrc);
        const size_t bsrc = (size_t)(bct * 128 + lrow) * 1024 + kk + lhalf * 8;
        CP16(st + 6144u, Bbase + bsrc);
    };
    auto compute_chunk = [&](int c) {
        const uint32_t off = sb + stage_off(c);
        uint32_t bt[4][2];
#pragma unroll
        for (int pr = 0; pr < 2; pr++) {
            uint32_t q[4];
            ldsm4(q, off + 6144u + (uint32_t)((wn * 32 + pr * 16) * 48) + bLane);
            bt[2 * pr][0]     = q[0]; bt[2 * pr][1]     = q[1];
            bt[2 * pr + 1][0] = q[2]; bt[2 * pr + 1][1] = q[3];
        }
        uint32_t at[4][4];
#pragma unroll
        for (int mt = 0; mt < 4; mt++)
            ldsm4(at[mt], off + (uint32_t)((wm * 64 + mt * 16) * 48) + aLane);
#pragma unroll
        for (int mt = 0; mt < 4; mt++)
#pragma unroll
            for (int nt = 0; nt < 4; nt++)
                mma_fp16(acc[mt][nt], at[mt], bt[nt]);
    };

    // prologue: chunks 0..4 in flight (5 groups)
    load_chunk(0); CPCOMMIT();
    load_chunk(1); CPCOMMIT();
    load_chunk(2); CPCOMMIT();
    load_chunk(3); CPCOMMIT();
    load_chunk(4); CPCOMMIT();

    for (int c = 0; c < 64; c++) {
        CPWAIT4();               // chunk c resident (<=4 groups pending)
        __syncthreads();         // stage (c-1)%6 reusable by load below
        if (c + 5 < 64) load_chunk(c + 5);
        CPCOMMIT();
        compute_chunk(c);
    }

    // ---- epilogue ----
    const int g = lane >> 2, cp2 = (lane & 3) * 2;
    const size_t cbase = (size_t)bp * PLANE + (size_t)rt * 131072 + (size_t)bct * CCB;
#pragma unroll
    for (int mt = 0; mt < 4; mt++) {
#pragma unroll
        for (int nt = 0; nt < 4; nt++) {
            int r0 = wm * 64 + mt * 16 + g;
            int col = wn * 32 + nt * 8 + cp2;
            float v0 = acc[mt][nt][0], v1 = acc[mt][nt][1];
            float v2 = acc[mt][nt][2], v3 = acc[mt][nt][3];
            size_t o0 = cbase + (size_t)r0 * CRI + col;
            size_t o1 = cbase + (size_t)(r0 + 8) * CRI + col;
            if (Cf) {
                float b0 = bias[bct * 128 + col], b1 = bias[bct * 128 + col + 1];
                *(float2*)(Cf + o0) = make_float2(v0 + b0, v1 + b1);
                *(float2*)(Cf + o1) = make_float2(v2 + b0, v3 + b1);
            } else {
                *(uint32_t*)(Ch + o0) = packh2(v0, v1);
                *(uint32_t*)(Ch + o1) = packh2(v2, v3);
            }
        }
    }
}

// ======================= fp16 mma attention (register-resident P) ============
// One CTA per (b,h). Warp w owns rows w*16..w*16+15 (full 128 cols).
// B-fragment software pipelining: ldsm for gp+1 issued before MMAs of gp
// (attn is latency-bound at 8 warps/SM; hides trans-ldsm latency).
// smem: Q stages@0 (4 x 6144: 128 rows x 48B),
//       K/V stages@24576 (4 x 4352: 16 rows x 272B). total 41984.
#define ATT_SMEM 41984
#define ATT_KST  24576u

__global__ __launch_bounds__(256, 1) void attn_mma(
    const __half* __restrict__ qkv, __half* __restrict__ atth)
{
    extern __shared__ __align__(1024) char smem[];
    const uint32_t sb = s2u(smem);
    const int tid = threadIdx.x;
    const int lane = tid & 31, w = tid >> 5;
    const size_t bhoff = (size_t)blockIdx.x * 16384;

    // plane order in qkv: 0 qw, 1 kw, 2 vw, 3 qp, 4 kp, 5 qc, 6 kc
    const int qpl[3] = { 0, 3, 5 }, kpl[3] = { 1, 4, 6 };

    const int s8 = lane >> 3, r8 = lane & 7;
    const uint32_t aLane = (uint32_t)(((s8 & 1) * 8 + r8) * 48 + (s8 >> 1) * 16);
    const uint32_t kr = (uint32_t)(lane & 15);
    const uint32_t nf = (uint32_t)((lane >> 4) * 8);
    const uint32_t wrow48 = (uint32_t)(w * 16 * 48);

    const int qrow = tid >> 1, qhalf = tid & 1;
    const uint32_t qdst = (uint32_t)(qrow * 48 + qhalf * 16);
    const int krow = tid >> 4, kseg = tid & 15;
    const uint32_t kdst = (uint32_t)(krow * 272 + kseg * 16);

    auto loadQK = [&](int it) {
        int s = it >> 3, c = it & 7;
        uint32_t qs = sb + (uint32_t)((it & 3) * 6144) + qdst;
        size_t qsrc = (size_t)qpl[s] * PLANE + bhoff + (size_t)qrow * 128 + c * 16 + qhalf * 8;
        CP16(qs, qkv + qsrc);
        uint32_t ks = sb + ATT_KST + (uint32_t)((it & 3) * 4352) + kdst;
        size_t ksrc = (size_t)kpl[s] * PLANE + bhoff + (size_t)(c * 16 + krow) * 128 + kseg * 8;
        CP16(ks, qkv + ksrc);
    };
    auto loadV = [&](int v) {
        uint32_t ks = sb + ATT_KST + (uint32_t)((v & 3) * 4352) + kdst;
        size_t ksrc = 2ull * PLANE + bhoff + (size_t)(v * 16 + krow) * 128 + kseg * 8;
        CP16(ks, qkv + ksrc);
    };

    float acc[16][4];
#pragma unroll
    for (int i = 0; i < 16; i++)
#pragma unroll
        for (int j = 0; j < 4; j++) acc[i][j] = 0.f;

    loadQK(0); CPCOMMIT();
    loadQK(1); CPCOMMIT();
    loadQK(2); CPCOMMIT();

    // ---- Phase 1: sim (24 iters = 3 streams x 8 k-chunks; 16 MMA/iter) ----
    for (int it = 0; it < 24; it++) {
        CPWAIT2();
        __syncthreads();
        if (it + 3 < 24) loadQK(it + 3);
        CPCOMMIT();

        const uint32_t qs = sb + (uint32_t)((it & 3) * 6144);
        const uint32_t ks = sb + ATT_KST + (uint32_t)((it & 3) * 4352);
        uint32_t ah[4];
        ldsm4(ah, qs + wrow48 + aLane);
        uint32_t bb[2][8];
        ldsm4t(bb[0],     ks + kr * 272 + (0 * 16 + nf) * 2);
        ldsm4t(bb[0] + 4, ks + kr * 272 + (1 * 16 + nf) * 2);
#pragma unroll
        for (int gp = 0; gp < 4; gp++) {
            uint32_t* cur = bb[gp & 1];
            if (gp < 3) {
                uint32_t* nxt = bb[(gp + 1) & 1];
                ldsm4t(nxt,     ks + kr * 272 + ((2 * gp + 2) * 16 + nf) * 2);
                ldsm4t(nxt + 4, ks + kr * 272 + ((2 * gp + 3) * 16 + nf) * 2);
            }
            mma_fp16(acc[4 * gp],     ah, cur);
            mma_fp16(acc[4 * gp + 1], ah, cur + 2);
            mma_fp16(acc[4 * gp + 2], ah, cur + 4);
            mma_fp16(acc[4 * gp + 3], ah, cur + 6);
        }
    }

    // drain QK traffic, then prefetch V into stages 0..2 (overlaps softmax)
    CPWAIT0();
    __syncthreads();
    loadV(0); CPCOMMIT();
    loadV(1); CPCOMMIT();
    loadV(2); CPCOMMIT();

    // ---- Phase 2: softmax (warp-local; lane rows g and g+8) ----
    const float SC = 0.08838834764831845f;   // 128^-0.5
    float m0 = -1e30f, m1 = -1e30f;
#pragma unroll
    for (int nt = 0; nt < 16; nt++) {
#pragma unroll
        for (int j = 0; j < 4; j++) acc[nt][j] *= SC;
        m0 = fmaxf(m0, fmaxf(acc[nt][0], acc[nt][1]));
        m1 = fmaxf(m1, fmaxf(acc[nt][2], acc[nt][3]));
    }
    m0 = fmaxf(m0, __shfl_xor_sync(0xffffffffu, m0, 1));
    m0 = fmaxf(m0, __shfl_xor_sync(0xffffffffu, m0, 2));
    m1 = fmaxf(m1, __shfl_xor_sync(0xffffffffu, m1, 1));
    m1 = fmaxf(m1, __shfl_xor_sync(0xffffffffu, m1, 2));
    float sum0 = 0.f, sum1 = 0.f;
#pragma unroll
    for (int nt = 0; nt < 16; nt++) {
        acc[nt][0] = __expf(acc[nt][0] - m0); sum0 += acc[nt][0];
        acc[nt][1] = __expf(acc[nt][1] - m0); sum0 += acc[nt][1];
        acc[nt][2] = __expf(acc[nt][2] - m1); sum1 += acc[nt][2];
        acc[nt][3] = __expf(acc[nt][3] - m1); sum1 += acc[nt][3];
    }
    sum0 += __shfl_xor_sync(0xffffffffu, sum0, 1);
    sum0 += __shfl_xor_sync(0xffffffffu, sum0, 2);
    sum1 += __shfl_xor_sync(0xffffffffu, sum1, 1);
    sum1 += __shfl_xor_sync(0xffffffffu, sum1, 2);
    const float inv0 = 1.f / sum0, inv1 = 1.f / sum1;

    // ---- repack P into fp16 A-fragments (C-frag layout == A-frag layout) ----
    uint32_t pf[8][4];
#pragma unroll
    for (int c = 0; c < 8; c++) {
        pf[c][0] = packh2(acc[2*c][0]   * inv0, acc[2*c][1]   * inv0);
        pf[c][1] = packh2(acc[2*c][2]   * inv1, acc[2*c][3]   * inv1);
        pf[c][2] = packh2(acc[2*c+1][0] * inv0, acc[2*c+1][1] * inv0);
        pf[c][3] = packh2(acc[2*c+1][2] * inv1, acc[2*c+1][3] * inv1);
    }
#pragma unroll
    for (int i = 0; i < 16; i++)
#pragma unroll
        for (int j = 0; j < 4; j++) acc[i][j] = 0.f;

    // ---- Phase 3: out = P * V (8 k-chunks; 16 MMA/chunk) ----
    for (int v = 0; v < 8; v++) {
        CPWAIT2();
        __syncthreads();
        if (v + 3 < 8) loadV(v + 3);
        CPCOMMIT();

        const uint32_t ks = sb + ATT_KST + (uint32_t)((v & 3) * 4352);
        uint32_t bb[2][8];
        ldsm4t(bb[0],     ks + kr * 272 + (0 * 16 + nf) * 2);
        ldsm4t(bb[0] + 4, ks + kr * 272 + (1 * 16 + nf) * 2);
#pragma unroll
        for (int gp = 0; gp < 4; gp++) {
            uint32_t* cur = bb[gp & 1];
            if (gp < 3) {
                uint32_t* nxt = bb[(gp + 1) & 1];
                ldsm4t(nxt,     ks + kr * 272 + ((2 * gp + 2) * 16 + nf) * 2);
                ldsm4t(nxt + 4, ks + kr * 272 + ((2 * gp + 3) * 16 + nf) * 2);
            }
            mma_fp16(acc[4 * gp],     pf[v], cur);
            mma_fp16(acc[4 * gp + 1], pf[v], cur + 2);
            mma_fp16(acc[4 * gp + 2], pf[v], cur + 4);
            mma_fp16(acc[4 * gp + 3], pf[v], cur + 6);
        }
    }

    // ---- write att as fp16 plane ----
    {
        const int g = lane >> 2, c2 = (lane & 3) * 2;
        const size_t r0 = bhoff + (size_t)(w * 16 + g) * 128;
#pragma unroll
        for (int nt = 0; nt < 16; nt++) {
            int col = nt * 8 + c2;
            *(uint32_t*)(atth + r0 + col) = packh2(acc[nt][0], acc[nt][1]);
            *(uint32_t*)(atth + r0 + 8 * 128 + col) = packh2(acc[nt][2], acc[nt][3]);
        }
    }
}

// ======================= launch ==============================================
extern "C" void kernel_launch(void* const* d_in, const int* in_sizes, int n_in,
                              void* d_out, int out_size)
{
    (void)in_sizes; (void)n_in; (void)out_size;
    const float* inp[3] = { (const float*)d_in[0], (const float*)d_in[1],
                            (const float*)d_in[2] };
    const float* W[8] = { (const float*)d_in[3], (const float*)d_in[4],
                          (const float*)d_in[5], (const float*)d_in[6],
                          (const float*)d_in[7], (const float*)d_in[8],
                          (const float*)d_in[9], (const float*)d_in[10] };
    const float* bo = (const float*)d_in[11];
    float* out = (float*)d_out;

    void* symp = nullptr;
    cudaGetSymbolAddress(&symp, g_bf);
    bf16* P = (bf16*)symp;
    __half* infp = (__half*)P;                    // 3 fp16 input planes  [0,3)
    __half* qkvh = (__half*)(P + 3ull * PLANE);   // 7 fp16 q/k/v planes  [3,10)
    __half* atth = (__half*)(P + 10ull * PLANE);  // 1 fp16 att plane     [10,11)
    __half* wfp  = (__half*)(P + 11ull * PLANE);  // 8 fp16 weight planes

    cudaFuncSetAttribute(gemm_fp, cudaFuncAttributeMaxDynamicSharedMemorySize, GEMM_SMEM);
    cudaFuncSetAttribute(attn_mma, cudaFuncAttributeMaxDynamicSharedMemorySize, ATT_SMEM);

    // 0) fused prep: 8 weight transposes + 3 input conversions (one launch)
    prep_all<<<dim3(1024, 11), 256>>>(
        W[0], W[1], W[2], W[3], W[4], W[5], W[6], W[7],
        inp[0], inp[1], inp[2], wfp, infp);

    // 1) ALL projections in one launch -> fp16 q/k/v planes (head layout)
    gemm_fp<<<dim3(56, 128), 256, GEMM_SMEM>>>(
        infp, wfp, nullptr, qkvh, nullptr, 128, 1024, 16384, 128, 1);

    // 2) attention (all-fp16, B-frag pipelined) -> fp16 att plane
    attn_mma<<<1024, 256, ATT_SMEM>>>(qkvh, atth);

    // 3) final GEMM: att * Wo^T + bias -> f32 out (row-major)
    gemm_fp<<<dim3(8, 128), 256, GEMM_SMEM>>>(
        atth, wfp + 7ull * WPLANE,
        out, nullptr, bo, 16384, 128, 128, 1024, 0);
}

// round 17
// speedup vs baseline: 1.1702x; 1.0223x over previous
#include <cuda_runtime.h>
#include <cuda_bf16.h>
#include <cuda_fp16.h>
#include <cstdint>

// Problem: B=128, N=128, D=1024, H=8, HD=128, M = B*N = 16384
#define PLANE    (16384ull * 1024ull)   // activation plane elems (2B units)
#define WPLANE   (1024ull * 1024ull)    // weight plane elems
__device__ __align__(1024) __nv_bfloat16 g_bf[22ull * PLANE + 32ull * WPLANE];

typedef __nv_bfloat16 bf16;

// ======================= PTX helpers =========================================
__device__ __forceinline__ uint32_t s2u(const void* p) {
    uint32_t a;
    asm("{ .reg .u64 t; cvta.to.shared.u64 t, %1; cvt.u32.u64 %0, t; }"
        : "=r"(a) : "l"(p));
    return a;
}
__device__ __forceinline__ void ldsm4(uint32_t* r, uint32_t addr) {
    asm volatile("ldmatrix.sync.aligned.m8n8.x4.shared.b16 {%0,%1,%2,%3}, [%4];"
                 : "=r"(r[0]), "=r"(r[1]), "=r"(r[2]), "=r"(r[3]) : "r"(addr));
}
__device__ __forceinline__ void ldsm4t(uint32_t* r, uint32_t addr) {
    asm volatile("ldmatrix.sync.aligned.m8n8.x4.trans.shared.b16 {%0,%1,%2,%3}, [%4];"
                 : "=r"(r[0]), "=r"(r[1]), "=r"(r[2]), "=r"(r[3]) : "r"(addr));
}
__device__ __forceinline__ void mma_fp16(float* d, const uint32_t* a, const uint32_t* b) {
    asm volatile(
        "mma.sync.aligned.m16n8k16.row.col.f32.f16.f16.f32 "
        "{%0,%1,%2,%3},{%4,%5,%6,%7},{%8,%9},{%0,%1,%2,%3};"
        : "+f"(d[0]), "+f"(d[1]), "+f"(d[2]), "+f"(d[3])
        : "r"(a[0]), "r"(a[1]), "r"(a[2]), "r"(a[3]), "r"(b[0]), "r"(b[1]));
}
#define CP16(dst, src) \
    asm volatile("cp.async.cg.shared.global [%0], [%1], 16;" :: "r"(dst), "l"(src))
#define CPCOMMIT() asm volatile("cp.async.commit_group;" ::: "memory")
#define CPWAIT4()  asm volatile("cp.async.wait_group 4;" ::: "memory")
#define CPWAIT2()  asm volatile("cp.async.wait_group 2;" ::: "memory")
#define CPWAIT0()  asm volatile("cp.async.wait_group 0;" ::: "memory")

__device__ __forceinline__ uint32_t packh2(float x0, float x1) {
    __half2 h; h.x = __float2half_rn(x0); h.y = __float2half_rn(x1);
    return *(uint32_t*)&h;
}

// ======================= fused prep: transpose 8 weights + convert 3 inputs ===
__global__ __launch_bounds__(256) void prep_all(
    const float* __restrict__ w0, const float* __restrict__ w1,
    const float* __restrict__ w2, const float* __restrict__ w3,
    const float* __restrict__ w4, const float* __restrict__ w5,
    const float* __restrict__ w6, const float* __restrict__ w7,
    const float* __restrict__ i0, const float* __restrict__ i1,
    const float* __restrict__ i2,
    __half* __restrict__ wout, __half* __restrict__ iout)
{
    const int z = blockIdx.y;
    const int tid = threadIdx.x;
    if (z < 8) {
        const float* srcs[8] = { w0, w1, w2, w3, w4, w5, w6, w7 };
        const float* src = srcs[z];
        __half* o = wout + (size_t)z * WPLANE;
        __shared__ float t[32][33];
        int bx = (blockIdx.x & 31) * 32, by = (blockIdx.x >> 5) * 32;
        int tx = tid & 31, ty = tid >> 5;
#pragma unroll
        for (int i = ty; i < 32; i += 8)
            t[i][tx] = src[(size_t)(by + i) * 1024 + bx + tx];
        __syncthreads();
#pragma unroll
        for (int i = ty; i < 32; i += 8)
            o[(size_t)(bx + i) * 1024 + by + tx] = __float2half_rn(t[tx][i]);
    } else {
        const float* src = (z == 8) ? i0 : (z == 9) ? i1 : i2;
        __half* o = iout + (size_t)(z - 8) * PLANE;
        size_t base = (size_t)blockIdx.x * 16384 + tid * 4;
#pragma unroll
        for (int it = 0; it < 16; it++) {
            size_t i4 = base + (size_t)it * 1024;
            float4 v = *(const float4*)(src + i4);
            *(uint32_t*)(o + i4)     = packh2(v.x, v.y);
            *(uint32_t*)(o + i4 + 2) = packh2(v.z, v.w);
        }
    }
}

// ======================= single-pass fp16 mma.sync GEMM (round-14 proven) ====
// CTA 128x128, 256 thr, warp tile 64x32 (2x4 warp grid), 2 CTAs/SM.
// 6-stage ring, per-chunk commit, wait_group 4 (distance 5).
// smem stage: A@0 (128 rows x 48B), B@6144 (128 x 48B); stage stride 12288.
#define GEMM_STAGES 6
#define GEMM_SMEM (GEMM_STAGES * 12288)

__global__ __launch_bounds__(256, 2) void gemm_fp(
    const __half* __restrict__ A, const __half* __restrict__ B,
    float* __restrict__ Cf, __half* __restrict__ Ch,
    const float* __restrict__ bias, int ACB, int ARI, int CCB, int CRI, int mode)
{
    extern __shared__ __align__(1024) char smem[];
    const uint32_t sb = s2u(smem);
    const int tid = threadIdx.x;
    const int lane = tid & 31, wid = tid >> 5;
    const int rt = blockIdx.y, ct = blockIdx.x;

    int ap, bp, bct;
    if (mode) {
        if (ct < 24)      { ap = 0; bp = ct >> 3;              bct = ct & 7; }
        else if (ct < 40) { ap = 1; bp = 3 + ((ct - 24) >> 3); bct = (ct - 24) & 7; }
        else              { ap = 2; bp = 5 + ((ct - 40) >> 3); bct = (ct - 40) & 7; }
    } else { ap = 0; bp = 0; bct = ct; }

    const int wm = wid & 1, wn = wid >> 1;
    const int s8 = lane >> 3, r8 = lane & 7;
    const uint32_t aLane = (uint32_t)(((s8 & 1) * 8 + r8) * 48 + (s8 >> 1) * 16);
    const uint32_t bLane = (uint32_t)(((s8 >> 1) * 8 + r8) * 48 + (s8 & 1) * 16);

    const int lrow = tid >> 1, lhalf = tid & 1;
    const uint32_t dstoff = (uint32_t)(lrow * 48 + lhalf * 16);
    const __half* Abase = A + (size_t)ap * PLANE;
    const __half* Bbase = B + (size_t)bp * WPLANE;

    float acc[4][4][4];
#pragma unroll
    for (int i = 0; i < 4; i++)
#pragma unroll
        for (int j = 0; j < 4; j++)
#pragma unroll
            for (int k = 0; k < 4; k++) acc[i][j][k] = 0.f;

    auto stage_off = [&](int c) -> uint32_t {
        return (uint32_t)((c % GEMM_STAGES) * 12288);
    };
    auto load_chunk = [&](int c) {
        const int kk = c * 16;
        const uint32_t st = sb + stage_off(c) + dstoff;
        const size_t asrc = (size_t)rt * 131072 + (size_t)(kk >> 7) * ACB
                          + (size_t)lrow * ARI + (kk & 127) + lhalf * 8;
        CP16(st, Abase + asrc);
        const size_t bsrc = (size_t)(bct * 128 + lrow) * 1024 + kk + lhalf * 8;
        CP16(st + 6144u, Bbase + bsrc);
    };
    auto compute_chunk = [&](int c) {
        const uint32_t off = sb + stage_off(c);
        uint32_t bt[4][2];
#pragma unroll
        for (int pr = 0; pr < 2; pr++) {
            uint32_t q[4];
            ldsm4(q, off + 6144u + (uint32_t)((wn * 32 + pr * 16) * 48) + bLane);
            bt[2 * pr][0]     = q[0]; bt[2 * pr][1]     = q[1];
            bt[2 * pr + 1][0] = q[2]; bt[2 * pr + 1][1] = q[3];
        }
        uint32_t at[4][4];
#pragma unroll
        for (int mt = 0; mt < 4; mt++)
            ldsm4(at[mt], off + (uint32_t)((wm * 64 + mt * 16) * 48) + aLane);
#pragma unroll
        for (int mt = 0; mt < 4; mt++)
#pragma unroll
            for (int nt = 0; nt < 4; nt++)
                mma_fp16(acc[mt][nt], at[mt], bt[nt]);
    };

    load_chunk(0); CPCOMMIT();
    load_chunk(1); CPCOMMIT();
    load_chunk(2); CPCOMMIT();
    load_chunk(3); CPCOMMIT();
    load_chunk(4); CPCOMMIT();

    for (int c = 0; c < 64; c++) {
        CPWAIT4();
        __syncthreads();
        if (c + 5 < 64) load_chunk(c + 5);
        CPCOMMIT();
        compute_chunk(c);
    }

    // ---- epilogue ----
    const int g = lane >> 2, cp2 = (lane & 3) * 2;
    const size_t cbase = (size_t)bp * PLANE + (size_t)rt * 131072 + (size_t)bct * CCB;
#pragma unroll
    for (int mt = 0; mt < 4; mt++) {
#pragma unroll
        for (int nt = 0; nt < 4; nt++) {
            int r0 = wm * 64 + mt * 16 + g;
            int col = wn * 32 + nt * 8 + cp2;
            float v0 = acc[mt][nt][0], v1 = acc[mt][nt][1];
            float v2 = acc[mt][nt][2], v3 = acc[mt][nt][3];
            size_t o0 = cbase + (size_t)r0 * CRI + col;
            size_t o1 = cbase + (size_t)(r0 + 8) * CRI + col;
            if (Cf) {
                float b0 = bias[bct * 128 + col], b1 = bias[bct * 128 + col + 1];
                *(float2*)(Cf + o0) = make_float2(v0 + b0, v1 + b1);
                *(float2*)(Cf + o1) = make_float2(v2 + b0, v3 + b1);
            } else {
                *(uint32_t*)(Ch + o0) = packh2(v0, v1);
                *(uint32_t*)(Ch + o1) = packh2(v2, v3);
            }
        }
    }
}

// ======================= fp16 mma attention (P via smem, 2 CTAs/SM) ==========
// One CTA per (b,h). Warp w owns rows w*16..w*16+15 (full 128 cols).
// P stored to smem (272B-stride, validated r4-r7 layout) to cut register
// footprint below 128 -> 2 CTAs/SM. Same fp16 bits, same MMA order.
// smem: Q stages@0 (4 x 6144), K/V stages@24576 (4 x 4352),
//       P@41984 (128 rows x 272B = 34816). total 76800.
#define ATT_SMEM 76800
#define ATT_KST  24576u
#define ATT_P    41984u

__global__ __launch_bounds__(256, 2) void attn_mma(
    const __half* __restrict__ qkv, __half* __restrict__ atth)
{
    extern __shared__ __align__(1024) char smem[];
    const uint32_t sb = s2u(smem);
    const int tid = threadIdx.x;
    const int lane = tid & 31, w = tid >> 5;
    const size_t bhoff = (size_t)blockIdx.x * 16384;

    // plane order in qkv: 0 qw, 1 kw, 2 vw, 3 qp, 4 kp, 5 qc, 6 kc
    const int qpl[3] = { 0, 3, 5 }, kpl[3] = { 1, 4, 6 };

    const int s8 = lane >> 3, r8 = lane & 7;
    const uint32_t aLane = (uint32_t)(((s8 & 1) * 8 + r8) * 48 + (s8 >> 1) * 16);
    const uint32_t aPL   = (uint32_t)(((s8 & 1) * 8 + r8) * 272 + (s8 >> 1) * 16);
    const uint32_t kr = (uint32_t)(lane & 15);
    const uint32_t nf = (uint32_t)((lane >> 4) * 8);
    const uint32_t wrow48  = (uint32_t)(w * 16 * 48);
    const uint32_t wrow272 = (uint32_t)(w * 16 * 272);

    const int qrow = tid >> 1, qhalf = tid & 1;
    const uint32_t qdst = (uint32_t)(qrow * 48 + qhalf * 16);
    const int krow = tid >> 4, kseg = tid & 15;
    const uint32_t kdst = (uint32_t)(krow * 272 + kseg * 16);

    auto loadQK = [&](int it) {
        int s = it >> 3, c = it & 7;
        uint32_t qs = sb + (uint32_t)((it & 3) * 6144) + qdst;
        size_t qsrc = (size_t)qpl[s] * PLANE + bhoff + (size_t)qrow * 128 + c * 16 + qhalf * 8;
        CP16(qs, qkv + qsrc);
        uint32_t ks = sb + ATT_KST + (uint32_t)((it & 3) * 4352) + kdst;
        size_t ksrc = (size_t)kpl[s] * PLANE + bhoff + (size_t)(c * 16 + krow) * 128 + kseg * 8;
        CP16(ks, qkv + ksrc);
    };
    auto loadV = [&](int v) {
        uint32_t ks = sb + ATT_KST + (uint32_t)((v & 3) * 4352) + kdst;
        size_t ksrc = 2ull * PLANE + bhoff + (size_t)(v * 16 + krow) * 128 + kseg * 8;
        CP16(ks, qkv + ksrc);
    };

    float acc[16][4];
#pragma unroll
    for (int i = 0; i < 16; i++)
#pragma unroll
        for (int j = 0; j < 4; j++) acc[i][j] = 0.f;

    loadQK(0); CPCOMMIT();
    loadQK(1); CPCOMMIT();
    loadQK(2); CPCOMMIT();

    // ---- Phase 1: sim (24 iters; B-frag pipelined; 16 MMA/iter) ----
    for (int it = 0; it < 24; it++) {
        CPWAIT2();
        __syncthreads();
        if (it + 3 < 24) loadQK(it + 3);
        CPCOMMIT();

        const uint32_t qs = sb + (uint32_t)((it & 3) * 6144);
        const uint32_t ks = sb + ATT_KST + (uint32_t)((it & 3) * 4352);
        uint32_t ah[4];
        ldsm4(ah, qs + wrow48 + aLane);
        uint32_t bb[2][8];
        ldsm4t(bb[0],     ks + kr * 272 + (0 * 16 + nf) * 2);
        ldsm4t(bb[0] + 4, ks + kr * 272 + (1 * 16 + nf) * 2);
#pragma unroll
        for (int gp = 0; gp < 4; gp++) {
            uint32_t* cur = bb[gp & 1];
            if (gp < 3) {
                uint32_t* nxt = bb[(gp + 1) & 1];
                ldsm4t(nxt,     ks + kr * 272 + ((2 * gp + 2) * 16 + nf) * 2);
                ldsm4t(nxt + 4, ks + kr * 272 + ((2 * gp + 3) * 16 + nf) * 2);
            }
            mma_fp16(acc[4 * gp],     ah, cur);
            mma_fp16(acc[4 * gp + 1], ah, cur + 2);
            mma_fp16(acc[4 * gp + 2], ah, cur + 4);
            mma_fp16(acc[4 * gp + 3], ah, cur + 6);
        }
    }

    // drain QK traffic, then prefetch V into stages 0..2 (overlaps softmax)
    CPWAIT0();
    __syncthreads();
    loadV(0); CPCOMMIT();
    loadV(1); CPCOMMIT();
    loadV(2); CPCOMMIT();

    // ---- Phase 2: softmax (warp-local; lane rows g and g+8) ----
    const float SC = 0.08838834764831845f;   // 128^-0.5
    float m0 = -1e30f, m1 = -1e30f;
#pragma unroll
    for (int nt = 0; nt < 16; nt++) {
#pragma unroll
        for (int j = 0; j < 4; j++) acc[nt][j] *= SC;
        m0 = fmaxf(m0, fmaxf(acc[nt][0], acc[nt][1]));
        m1 = fmaxf(m1, fmaxf(acc[nt][2], acc[nt][3]));
    }
    m0 = fmaxf(m0, __shfl_xor_sync(0xffffffffu, m0, 1));
    m0 = fmaxf(m0, __shfl_xor_sync(0xffffffffu, m0, 2));
    m1 = fmaxf(m1, __shfl_xor_sync(0xffffffffu, m1, 1));
    m1 = fmaxf(m1, __shfl_xor_sync(0xffffffffu, m1, 2));
    float sum0 = 0.f, sum1 = 0.f;
#pragma unroll
    for (int nt = 0; nt < 16; nt++) {
        acc[nt][0] = __expf(acc[nt][0] - m0); sum0 += acc[nt][0];
        acc[nt][1] = __expf(acc[nt][1] - m0); sum0 += acc[nt][1];
        acc[nt][2] = __expf(acc[nt][2] - m1); sum1 += acc[nt][2];
        acc[nt][3] = __expf(acc[nt][3] - m1); sum1 += acc[nt][3];
    }
    sum0 += __shfl_xor_sync(0xffffffffu, sum0, 1);
    sum0 += __shfl_xor_sync(0xffffffffu, sum0, 2);
    sum1 += __shfl_xor_sync(0xffffffffu, sum1, 1);
    sum1 += __shfl_xor_sync(0xffffffffu, sum1, 2);
    const float inv0 = 1.f / sum0, inv1 = 1.f / sum1;

    // ---- store P (fp16) to smem: rows owned by this warp, 272B stride ----
    {
        const int g = lane >> 2, c2 = (lane & 3) * 2;
        const uint32_t r0off = wrow272 + (uint32_t)(g * 272);
#pragma unroll
        for (int nt = 0; nt < 16; nt++) {
            uint32_t co = (uint32_t)((nt * 8 + c2) * 2);
            *(uint32_t*)(smem + ATT_P + r0off + co) =
                packh2(acc[nt][0] * inv0, acc[nt][1] * inv0);
            *(uint32_t*)(smem + ATT_P + r0off + 8 * 272 + co) =
                packh2(acc[nt][2] * inv1, acc[nt][3] * inv1);
            acc[nt][0] = acc[nt][1] = acc[nt][2] = acc[nt][3] = 0.f;
        }
    }
    __syncwarp();

    // ---- Phase 3: out = P * V (8 k-chunks; A-frags from smem) ----
    for (int v = 0; v < 8; v++) {
        CPWAIT2();
        __syncthreads();
        if (v + 3 < 8) loadV(v + 3);
        CPCOMMIT();

        const uint32_t ks = sb + ATT_KST + (uint32_t)((v & 3) * 4352);
        uint32_t pa[4];
        ldsm4(pa, sb + ATT_P + wrow272 + (uint32_t)(v * 32) + aPL);
        uint32_t bb[2][8];
        ldsm4t(bb[0],     ks + kr * 272 + (0 * 16 + nf) * 2);
        ldsm4t(bb[0] + 4, ks + kr * 272 + (1 * 16 + nf) * 2);
#pragma unroll
        for (int gp = 0; gp < 4; gp++) {
            uint32_t* cur = bb[gp & 1];
            if (gp < 3) {
                uint32_t* nxt = bb[(gp + 1) & 1];
                ldsm4t(nxt,     ks + kr * 272 + ((2 * gp + 2) * 16 + nf) * 2);
                ldsm4t(nxt + 4, ks + kr * 272 + ((2 * gp + 3) * 16 + nf) * 2);
            }
            mma_fp16(acc[4 * gp],     pa, cur);
            mma_fp16(acc[4 * gp + 1], pa, cur + 2);
            mma_fp16(acc[4 * gp + 2], pa, cur + 4);
            mma_fp16(acc[4 * gp + 3], pa, cur + 6);
        }
    }

    // ---- write att as fp16 plane ----
    {
        const int g = lane >> 2, c2 = (lane & 3) * 2;
        const size_t r0 = bhoff + (size_t)(w * 16 + g) * 128;
#pragma unroll
        for (int nt = 0; nt < 16; nt++) {
            int col = nt * 8 + c2;
            *(uint32_t*)(atth + r0 + col) = packh2(acc[nt][0], acc[nt][1]);
            *(uint32_t*)(atth + r0 + 8 * 128 + col) = packh2(acc[nt][2], acc[nt][3]);
        }
    }
}

// ======================= launch ==============================================
extern "C" void kernel_launch(void* const* d_in, const int* in_sizes, int n_in,
                              void* d_out, int out_size)
{
    (void)in_sizes; (void)n_in; (void)out_size;
    const float* inp[3] = { (const float*)d_in[0], (const float*)d_in[1],
                            (const float*)d_in[2] };
    const float* W[8] = { (const float*)d_in[3], (const float*)d_in[4],
                          (const float*)d_in[5], (const float*)d_in[6],
                          (const float*)d_in[7], (const float*)d_in[8],
                          (const float*)d_in[9], (const float*)d_in[10] };
    const float* bo = (const float*)d_in[11];
    float* out = (float*)d_out;

    void* symp = nullptr;
    cudaGetSymbolAddress(&symp, g_bf);
    bf16* P = (bf16*)symp;
    __half* infp = (__half*)P;                    // 3 fp16 input planes  [0,3)
    __half* qkvh = (__half*)(P + 3ull * PLANE);   // 7 fp16 q/k/v planes  [3,10)
    __half* atth = (__half*)(P + 10ull * PLANE);  // 1 fp16 att plane     [10,11)
    __half* wfp  = (__half*)(P + 11ull * PLANE);  // 8 fp16 weight planes

    cudaFuncSetAttribute(gemm_fp, cudaFuncAttributeMaxDynamicSharedMemorySize, GEMM_SMEM);
    cudaFuncSetAttribute(attn_mma, cudaFuncAttributeMaxDynamicSharedMemorySize, ATT_SMEM);

    // 0) fused prep: 8 weight transposes + 3 input conversions (one launch)
    prep_all<<<dim3(1024, 11), 256>>>(
        W[0], W[1], W[2], W[3], W[4], W[5], W[6], W[7],
        inp[0], inp[1], inp[2], wfp, infp);

    // 1) ALL projections in one launch -> fp16 q/k/v planes (head layout)
    gemm_fp<<<dim3(56, 128), 256, GEMM_SMEM>>>(
        infp, wfp, nullptr, qkvh, nullptr, 128, 1024, 16384, 128, 1);

    // 2) attention (all-fp16, P via smem, 2 CTAs/SM) -> fp16 att plane
    attn_mma<<<1024, 256, ATT_SMEM>>>(qkvh, atth);

    // 3) final GEMM: att * Wo^T + bias -> f32 out (row-major)
    gemm_fp<<<dim3(8, 128), 256, GEMM_SMEM>>>(
        atth, wfp + 7ull * WPLANE,
        out, nullptr, bo, 16384, 128, 128, 1024, 0);
}